// round 3
// baseline (speedup 1.0000x reference)
#include <cuda_runtime.h>
#include <cstdint>

// NCutsLoss:
//   acc(b,k,h,w)   = sum_{m,n} padded[b,k,h+m,w+n] * weight[b,0,h,w,m,n]   (9x9 window)
//   assocA[b,k]    = sum_{h,w} acc * seg
//   assocV[b,k]    = sum_{h,w} sum_weight * seg
//   out[b]         = 8.0 - sum_k assocA/assocV
//
// B=16, K=8, H=W=128, WIN=9, padded is 136x136.

#define BB   16
#define KK   8
#define HH   128
#define WW   128
#define WIN  9
#define WQ   (WIN * WIN)      // 81
#define PH   (HH + WIN - 1)   // 136
#define PW   (WW + WIN - 1)   // 136

#define TH   16               // h-rows per block
#define PROWS (TH + WIN - 1)  // 24 padded rows in smem
#define CHUNK (PROWS * PW)    // 3264 floats per k-plane
#define SMEM_FLOATS (KK * CHUNK)
#define SMEM_BYTES  (SMEM_FLOATS * 4)   // 104448

#define NTILES (HH / TH)      // 8 h-tiles per b
// partials: [b][htile][16]  (0..7 = assocA per k, 8..15 = assocV per k)
__device__ float g_part[BB * NTILES * 16];

__global__ __launch_bounds__(512, 1)
void ncuts_main_kernel(const float* __restrict__ seg,
                       const float* __restrict__ pad,
                       const float* __restrict__ wgt,
                       const float* __restrict__ sw)
{
    extern __shared__ float smem[];   // [k][row][col] : 8 x 24 x 136
    const int b  = blockIdx.y;
    const int h0 = blockIdx.x * TH;
    const int tx = threadIdx.x;       // 0..31  (lane)
    const int ty = threadIdx.y;       // 0..15  (warp = one h-row)
    const int tid = ty * 32 + tx;

    // ---- Fill padded-seg tile: 8 contiguous chunks (full 136-wide rows) ----
    // chunk k global offset: ((b*K + k)*PH + h0) * PW ; rows are 544B -> 16B aligned.
    {
        #pragma unroll
        for (int k = 0; k < KK; ++k) {
            const float4* src = reinterpret_cast<const float4*>(
                pad + ((size_t)(b * KK + k) * PH + h0) * PW);
            float4* dst = reinterpret_cast<float4*>(smem + k * CHUNK);
            for (int i = tid; i < CHUNK / 4; i += 512)
                dst[i] = src[i];
        }
    }
    __syncthreads();

    const int h  = h0 + ty;
    const int w0 = tx * 4;            // this thread's 4 outputs: w0..w0+3

    float acc[4][KK];
    #pragma unroll
    for (int p = 0; p < 4; ++p)
        #pragma unroll
        for (int k = 0; k < KK; ++k)
            acc[p][k] = 0.0f;

    // Thread's weight region: 1296 contiguous floats, 16B aligned
    // (idx = ((b*H + h)*W + w0)*81 is divisible by 4 since w0 = 4*tx).
    const float* wthread = wgt + (((size_t)b * HH + h) * WW + w0) * WQ;

    // ---- Main windowed accumulation (m fully unrolled: extraction offsets
    //      9m mod 4 become compile-time, keeping t[] in registers) ----
    #pragma unroll
    for (int m = 0; m < WIN; ++m) {
        float wr[4][WIN];
        #pragma unroll
        for (int p = 0; p < 4; ++p) {
            const float* ps = wthread + p * WQ;   // 324-float slice, 16B aligned
            if (m < 8) {
                const int a   = (9 * m) & ~3;     // aligned float4 start
                const int off = 9 * m - a;        // 0..3, compile-time
                float4 q0 = *reinterpret_cast<const float4*>(ps + a);
                float4 q1 = *reinterpret_cast<const float4*>(ps + a + 4);
                float4 q2 = *reinterpret_cast<const float4*>(ps + a + 8);
                float t[12] = { q0.x, q0.y, q0.z, q0.w,
                                q1.x, q1.y, q1.z, q1.w,
                                q2.x, q2.y, q2.z, q2.w };
                #pragma unroll
                for (int n = 0; n < WIN; ++n)
                    wr[p][n] = t[off + n];
            } else {
                // m == 8: floats [72, 81) — avoid reading past slice end.
                float4 q0 = *reinterpret_cast<const float4*>(ps + 72);
                float4 q1 = *reinterpret_cast<const float4*>(ps + 76);
                wr[p][0] = q0.x; wr[p][1] = q0.y; wr[p][2] = q0.z; wr[p][3] = q0.w;
                wr[p][4] = q1.x; wr[p][5] = q1.y; wr[p][6] = q1.z; wr[p][7] = q1.w;
                wr[p][8] = ps[80];
            }
        }

        const float* srow = smem + (ty + m) * PW + w0;
        #pragma unroll
        for (int k = 0; k < KK; ++k) {
            const float* rk = srow + k * CHUNK;
            float4 v0 = *reinterpret_cast<const float4*>(rk);
            float4 v1 = *reinterpret_cast<const float4*>(rk + 4);
            float4 v2 = *reinterpret_cast<const float4*>(rk + 8);
            float vals[12] = { v0.x, v0.y, v0.z, v0.w,
                               v1.x, v1.y, v1.z, v1.w,
                               v2.x, v2.y, v2.z, v2.w };
            #pragma unroll
            for (int n = 0; n < WIN; ++n) {
                #pragma unroll
                for (int p = 0; p < 4; ++p)
                    acc[p][k] = fmaf(vals[n + p], wr[p][n], acc[p][k]);
            }
        }
    }

    // ---- Multiply by seg / sum_weight and reduce ----
    float vA[KK], vV[KK];
    {
        float4 swv = *reinterpret_cast<const float4*>(
            sw + ((size_t)b * HH + h) * WW + w0);
        float swa[4] = { swv.x, swv.y, swv.z, swv.w };
        #pragma unroll
        for (int k = 0; k < KK; ++k) {
            float4 sg = *reinterpret_cast<const float4*>(
                seg + (((size_t)b * KK + k) * HH + h) * WW + w0);
            float s4[4] = { sg.x, sg.y, sg.z, sg.w };
            float a = 0.0f, v = 0.0f;
            #pragma unroll
            for (int p = 0; p < 4; ++p) {
                a = fmaf(acc[p][k], s4[p], a);
                v = fmaf(swa[p],    s4[p], v);
            }
            vA[k] = a; vV[k] = v;
        }
    }

    // warp reduction (32 lanes)
    #pragma unroll
    for (int off = 16; off > 0; off >>= 1) {
        #pragma unroll
        for (int k = 0; k < KK; ++k) {
            vA[k] += __shfl_xor_sync(0xFFFFFFFFu, vA[k], off);
            vV[k] += __shfl_xor_sync(0xFFFFFFFFu, vV[k], off);
        }
    }

    __shared__ float sred[16][16];   // [warp][0..7 A, 8..15 V]
    if (tx == 0) {
        #pragma unroll
        for (int k = 0; k < KK; ++k) {
            sred[ty][k]     = vA[k];
            sred[ty][8 + k] = vV[k];
        }
    }
    __syncthreads();
    if (tid < 16) {
        float s = 0.0f;
        #pragma unroll
        for (int wrp = 0; wrp < 16; ++wrp)
            s += sred[wrp][tid];
        g_part[(b * NTILES + blockIdx.x) * 16 + tid] = s;
    }
}

__global__ void ncuts_finalize_kernel(float* __restrict__ out)
{
    int b = threadIdx.x;
    if (b >= BB) return;
    float assoc = 0.0f;
    #pragma unroll
    for (int k = 0; k < KK; ++k) {
        float A = 0.0f, V = 0.0f;
        #pragma unroll
        for (int ht = 0; ht < NTILES; ++ht) {
            A += g_part[(b * NTILES + ht) * 16 + k];
            V += g_part[(b * NTILES + ht) * 16 + 8 + k];
        }
        assoc += A / V;
    }
    out[b] = 8.0f - assoc;
}

extern "C" void kernel_launch(void* const* d_in, const int* in_sizes, int n_in,
                              void* d_out, int out_size)
{
    // Identify inputs by element count (robust to ordering; all sizes distinct).
    const float *seg = nullptr, *pad = nullptr, *wgt = nullptr, *sw = nullptr;
    for (int i = 0; i < n_in; ++i) {
        int sz = in_sizes[i];
        if      (sz == BB * KK * HH * WW)            seg = (const float*)d_in[i];
        else if (sz == BB * KK * PH * PW)            pad = (const float*)d_in[i];
        else if (sz == BB * HH * WW * WQ)            wgt = (const float*)d_in[i];
        else if (sz == BB * HH * WW)                 sw  = (const float*)d_in[i];
    }
    float* out = (float*)d_out;

    // Opt in to >48KB dynamic smem (idempotent host API, not a stream op).
    cudaFuncSetAttribute(ncuts_main_kernel,
                         cudaFuncAttributeMaxDynamicSharedMemorySize, SMEM_BYTES);

    dim3 grid(NTILES, BB);     // 8 x 16 = 128 blocks, one wave on 148 SMs
    dim3 block(32, 16);        // 512 threads; warp = one h-row
    ncuts_main_kernel<<<grid, block, SMEM_BYTES>>>(seg, pad, wgt, sw);
    ncuts_finalize_kernel<<<1, 32>>>(out);
}

// round 4
// speedup vs baseline: 1.1576x; 1.1576x over previous
#include <cuda_runtime.h>
#include <cstdint>

// NCutsLoss, fused single kernel:
//   acc(b,k,h,w)   = sum_{m,n} padded[b,k,h+m,w+n] * weight[b,0,h,w,m,n]   (9x9 window)
//   assocA[b,k]    = sum_{h,w} acc * seg
//   assocV[b,k]    = sum_{h,w} sum_weight * seg
//   out[b]         = 8.0 - sum_k assocA/assocV
//
// B=16, K=8, H=W=128, WIN=9, padded is 136x136.

#define BB   16
#define KK   8
#define HH   128
#define WW   128
#define WIN  9
#define WQ   (WIN * WIN)      // 81
#define PH   (HH + WIN - 1)   // 136
#define PW   (WW + WIN - 1)   // 136

#define TH   16               // h-rows per block
#define PROWS (TH + WIN - 1)  // 24 padded rows in smem
#define CHUNK (PROWS * PW)    // 3264 floats per k-plane
#define SMEM_FLOATS (KK * CHUNK)
#define SMEM_BYTES  (SMEM_FLOATS * 4)   // 104448

#define NTILES (HH / TH)      // 8 h-tiles per b
#define NBLOCKS (BB * NTILES) // 128

// partials: [b][htile][16]  (0..7 = assocA per k, 8..15 = assocV per k)
__device__ float    g_part[BB * NTILES * 16];
__device__ unsigned g_ctr = 0;

__global__ __launch_bounds__(512, 1)
void ncuts_fused_kernel(const float* __restrict__ seg,
                        const float* __restrict__ pad,
                        const float* __restrict__ wgt,
                        const float* __restrict__ sw,
                        float* __restrict__ out)
{
    extern __shared__ float smem[];   // [k][row][col] : 8 x 24 x 136
    const int b  = blockIdx.y;
    const int h0 = blockIdx.x * TH;
    const int tx = threadIdx.x;       // 0..31  (lane)
    const int ty = threadIdx.y;       // 0..15  (warp = one h-row)
    const int tid = ty * 32 + tx;

    // ---- Fill padded-seg tile: 8 contiguous chunks (full 136-wide rows) ----
    {
        #pragma unroll
        for (int k = 0; k < KK; ++k) {
            const float4* src = reinterpret_cast<const float4*>(
                pad + ((size_t)(b * KK + k) * PH + h0) * PW);
            float4* dst = reinterpret_cast<float4*>(smem + k * CHUNK);
            for (int i = tid; i < CHUNK / 4; i += 512)
                dst[i] = src[i];
        }
    }
    __syncthreads();

    const int h  = h0 + ty;
    const int w0 = tx * 4;            // this thread's 4 outputs: w0..w0+3

    float acc[4][KK];
    #pragma unroll
    for (int p = 0; p < 4; ++p)
        #pragma unroll
        for (int k = 0; k < KK; ++k)
            acc[p][k] = 0.0f;

    // Thread's weight region: 4 slices of 81 contiguous floats, 16B aligned
    // (idx = ((b*H + h)*W + w0)*81 divisible by 4 since w0 = 4*tx).
    const float* wthread = wgt + (((size_t)b * HH + h) * WW + w0) * WQ;

    // ---- Main windowed accumulation.
    // Non-overlapping chunk schedule: each 16B chunk of the 4x324B weight
    // region is loaded exactly once (20 f4 + 1 scalar per slice).
    // Window m needs slice floats [9m, 9m+9); off = (9m) mod 4 = m & 3.
    float4 carry[4];
    #pragma unroll
    for (int m = 0; m < WIN; ++m) {
        const int off = m & 3;        // compile-time per unrolled m
        float t[4][12];
        #pragma unroll
        for (int p = 0; p < 4; ++p) {
            const float* ps = wthread + p * WQ;
            float4 a, bq, c;
            if (m == 0 || m == 4) {
                const int base = (m == 0) ? 0 : 36;
                a  = *reinterpret_cast<const float4*>(ps + base);
                bq = *reinterpret_cast<const float4*>(ps + base + 4);
                c  = *reinterpret_cast<const float4*>(ps + base + 8);
            } else if (m == 8) {
                // floats [72,81): 2 f4 + 1 scalar (no OOB past slice end)
                a  = *reinterpret_cast<const float4*>(ps + 72);
                bq = *reinterpret_cast<const float4*>(ps + 76);
                c  = make_float4(ps[80], 0.0f, 0.0f, 0.0f);
            } else {
                // fresh chunk index: m in {1,2,3}: 2m+1 ; m in {5,6,7}: 2m+2
                const int f = ((m <= 3) ? (2 * m + 1) : (2 * m + 2)) * 4;
                a  = carry[p];
                bq = *reinterpret_cast<const float4*>(ps + f);
                c  = *reinterpret_cast<const float4*>(ps + f + 4);
            }
            t[p][0] = a.x;  t[p][1] = a.y;  t[p][2]  = a.z;  t[p][3]  = a.w;
            t[p][4] = bq.x; t[p][5] = bq.y; t[p][6]  = bq.z; t[p][7]  = bq.w;
            t[p][8] = c.x;  t[p][9] = c.y;  t[p][10] = c.z;  t[p][11] = c.w;
            carry[p] = c;
        }

        const float* srow = smem + (ty + m) * PW + w0;
        #pragma unroll
        for (int k = 0; k < KK; ++k) {
            const float* rk = srow + k * CHUNK;
            float4 v0 = *reinterpret_cast<const float4*>(rk);
            float4 v1 = *reinterpret_cast<const float4*>(rk + 4);
            float4 v2 = *reinterpret_cast<const float4*>(rk + 8);
            float vals[12] = { v0.x, v0.y, v0.z, v0.w,
                               v1.x, v1.y, v1.z, v1.w,
                               v2.x, v2.y, v2.z, v2.w };
            #pragma unroll
            for (int n = 0; n < WIN; ++n) {
                #pragma unroll
                for (int p = 0; p < 4; ++p)
                    acc[p][k] = fmaf(vals[n + p], t[p][off + n], acc[p][k]);
            }
        }
    }

    // ---- Multiply by seg / sum_weight and reduce ----
    float vA[KK], vV[KK];
    {
        float4 swv = *reinterpret_cast<const float4*>(
            sw + ((size_t)b * HH + h) * WW + w0);
        float swa[4] = { swv.x, swv.y, swv.z, swv.w };
        #pragma unroll
        for (int k = 0; k < KK; ++k) {
            float4 sg = *reinterpret_cast<const float4*>(
                seg + (((size_t)b * KK + k) * HH + h) * WW + w0);
            float s4[4] = { sg.x, sg.y, sg.z, sg.w };
            float a = 0.0f, v = 0.0f;
            #pragma unroll
            for (int p = 0; p < 4; ++p) {
                a = fmaf(acc[p][k], s4[p], a);
                v = fmaf(swa[p],    s4[p], v);
            }
            vA[k] = a; vV[k] = v;
        }
    }

    // warp reduction (32 lanes)
    #pragma unroll
    for (int offs = 16; offs > 0; offs >>= 1) {
        #pragma unroll
        for (int k = 0; k < KK; ++k) {
            vA[k] += __shfl_xor_sync(0xFFFFFFFFu, vA[k], offs);
            vV[k] += __shfl_xor_sync(0xFFFFFFFFu, vV[k], offs);
        }
    }

    __shared__ float sred[16][16];   // [warp][0..7 A, 8..15 V]
    if (tx == 0) {
        #pragma unroll
        for (int k = 0; k < KK; ++k) {
            sred[ty][k]     = vA[k];
            sred[ty][8 + k] = vV[k];
        }
    }
    __syncthreads();
    if (tid < 16) {
        float s = 0.0f;
        #pragma unroll
        for (int wrp = 0; wrp < 16; ++wrp)
            s += sred[wrp][tid];
        g_part[(b * NTILES + blockIdx.x) * 16 + tid] = s;
        __threadfence();             // publish partials (release)
    }
    __syncthreads();

    // ---- Last-block finalize (fused; deterministic fixed-order sums) ----
    __shared__ unsigned s_last;
    __shared__ float fin[BB * 16];
    if (tid == 0) {
        unsigned old = atomicAdd(&g_ctr, 1u);
        s_last = (old == NBLOCKS - 1) ? 1u : 0u;
    }
    __syncthreads();
    if (s_last) {
        __threadfence();             // acquire all blocks' partials
        if (tid < BB * 16) {
            const int bb = tid >> 4, slot = tid & 15;
            float s = 0.0f;
            #pragma unroll
            for (int ht = 0; ht < NTILES; ++ht)
                s += g_part[(bb * NTILES + ht) * 16 + slot];
            fin[tid] = s;
        }
        __syncthreads();
        if (tid < BB) {
            float assoc = 0.0f;
            #pragma unroll
            for (int k = 0; k < KK; ++k)
                assoc += fin[tid * 16 + k] / fin[tid * 16 + 8 + k];
            out[tid] = 8.0f - assoc;
        }
        if (tid == 0) g_ctr = 0;     // reset for next graph replay
    }
}

extern "C" void kernel_launch(void* const* d_in, const int* in_sizes, int n_in,
                              void* d_out, int out_size)
{
    // Identify inputs by element count (robust to ordering; all sizes distinct).
    const float *seg = nullptr, *pad = nullptr, *wgt = nullptr, *sw = nullptr;
    for (int i = 0; i < n_in; ++i) {
        int sz = in_sizes[i];
        if      (sz == BB * KK * HH * WW)            seg = (const float*)d_in[i];
        else if (sz == BB * KK * PH * PW)            pad = (const float*)d_in[i];
        else if (sz == BB * HH * WW * WQ)            wgt = (const float*)d_in[i];
        else if (sz == BB * HH * WW)                 sw  = (const float*)d_in[i];
    }
    float* out = (float*)d_out;

    cudaFuncSetAttribute(ncuts_fused_kernel,
                         cudaFuncAttributeMaxDynamicSharedMemorySize, SMEM_BYTES);

    dim3 grid(NTILES, BB);     // 8 x 16 = 128 blocks, one wave on 148 SMs
    dim3 block(32, 16);        // 512 threads; warp = one h-row
    ncuts_fused_kernel<<<grid, block, SMEM_BYTES>>>(seg, pad, wgt, sw, out);
}